// round 4
// baseline (speedup 1.0000x reference)
#include <cuda_runtime.h>
#include <cuda_bf16.h>
#include <cstdint>

#define BSZ 512
#define DIM 128
#define MARGIN 0.2f

// Scratch (no allocations anywhere)
__device__ float g_dist[BSZ * BSZ];
__device__ float g_psum[BSZ];
__device__ int   g_pcnt[BSZ];
__device__ int   g_ctr;          // zero-init; last block resets -> replay-safe

// ---- packed f32x2 helpers (Blackwell) -------------------------------------
__device__ __forceinline__ unsigned long long add2(unsigned long long a,
                                                   unsigned long long b) {
    unsigned long long r;
    asm("add.rn.f32x2 %0, %1, %2;" : "=l"(r) : "l"(a), "l"(b));
    return r;
}
__device__ __forceinline__ unsigned long long fma2(unsigned long long a,
                                                   unsigned long long b,
                                                   unsigned long long c) {
    unsigned long long r;
    asm("fma.rn.f32x2 %0, %1, %2, %3;" : "=l"(r) : "l"(a), "l"(b), "l"(c));
    return r;
}
__device__ __forceinline__ float sum2(unsigned long long v) {
    float lo, hi;
    asm("mov.b64 {%0, %1}, %2;" : "=f"(lo), "=f"(hi) : "l"(v));
    return lo + hi;
}

// ---------------------------------------------------------------------------
// Kernel A: pairwise Euclidean dist, diff-based (matches reference's
// sum((a-b)^2)), packed f32x2: sub == add of negated B. 32x32 tile, 2x2 micro.
// ---------------------------------------------------------------------------
__global__ __launch_bounds__(256, 4)
void dist_kernel(const float* __restrict__ emb) {
    __shared__ float sA[32][130];   // 128 + 2 pad (odd ull stride)
    __shared__ float sB[32][130];   // NEGATED B rows

    const int tx = threadIdx.x, ty = threadIdx.y;
    const int tid = ty * 16 + tx;
    const int i0 = blockIdx.y * 32;
    const int j0 = blockIdx.x * 32;

    #pragma unroll
    for (int t = tid; t < 1024; t += 256) {
        const int row = t >> 5;
        const int c4  = t & 31;
        const float4 va = *(const float4*)(emb + (size_t)(i0 + row) * DIM + c4 * 4);
        float2* da = (float2*)&sA[row][c4 * 4];
        da[0] = make_float2(va.x, va.y);
        da[1] = make_float2(va.z, va.w);
        const float4 vb = *(const float4*)(emb + (size_t)(j0 + row) * DIM + c4 * 4);
        float2* db = (float2*)&sB[row][c4 * 4];
        db[0] = make_float2(-vb.x, -vb.y);
        db[1] = make_float2(-vb.z, -vb.w);
    }
    __syncthreads();

    const unsigned long long* A0 = (const unsigned long long*)sA[ty * 2 + 0];
    const unsigned long long* A1 = (const unsigned long long*)sA[ty * 2 + 1];
    const unsigned long long* B0 = (const unsigned long long*)sB[tx * 2 + 0];
    const unsigned long long* B1 = (const unsigned long long*)sB[tx * 2 + 1];

    unsigned long long acc00 = 0ull, acc01 = 0ull, acc10 = 0ull, acc11 = 0ull;

    #pragma unroll 16
    for (int k2 = 0; k2 < 64; k2++) {
        const unsigned long long a0 = A0[k2];
        const unsigned long long a1 = A1[k2];
        const unsigned long long b0 = B0[k2];
        const unsigned long long b1 = B1[k2];
        unsigned long long t;
        t = add2(a0, b0); acc00 = fma2(t, t, acc00);
        t = add2(a0, b1); acc01 = fma2(t, t, acc01);
        t = add2(a1, b0); acc10 = fma2(t, t, acc10);
        t = add2(a1, b1); acc11 = fma2(t, t, acc11);
    }

    const int i = i0 + ty * 2;
    const int j = j0 + tx * 2;
    const float s00 = sum2(acc00), s01 = sum2(acc01);
    const float s10 = sum2(acc10), s11 = sum2(acc11);
    g_dist[(size_t)(i + 0) * BSZ + (j + 0)] = s00 > 0.f ? sqrtf(s00) : 0.f;
    g_dist[(size_t)(i + 0) * BSZ + (j + 1)] = s01 > 0.f ? sqrtf(s01) : 0.f;
    g_dist[(size_t)(i + 1) * BSZ + (j + 0)] = s10 > 0.f ? sqrtf(s10) : 0.f;
    g_dist[(size_t)(i + 1) * BSZ + (j + 1)] = s11 > 0.f ? sqrtf(s11) : 0.f;
}

// ---------------------------------------------------------------------------
// Kernel B: block-per-row mining (512 blocks x 512 thr) + fused finalize.
// Per valid pair (i<p, same label):
//   j_min = first j: neg[j] && d_ap < d[i,j] < d_ap+margin
//   found  -> d_an = d[i, rank(j_min)]   (reference quirk: neg-rank index)
//   !found -> d_an = d[i, j0]            (j0 = first negative, else 0)
//   loss  += relu(d_ap^2 - d_an^2 + margin)
// Parallelism: 16 warps stride over candidate p; per-lane early-exit scan.
// Rank via popcount over ballot masks (no block-wide scan).
// ---------------------------------------------------------------------------
__global__ __launch_bounds__(BSZ, 2)
void mine_kernel(const int* __restrict__ labels, float* __restrict__ out) {
    __shared__ float    drow[BSZ];
    __shared__ unsigned nmask[16];      // neg ballot words for this row
    __shared__ float    wsum[16];
    __shared__ int      sLast;

    const int i    = blockIdx.x;
    const int tid  = threadIdx.x;
    const int warp = tid >> 5;
    const int lane = tid & 31;

    drow[tid] = g_dist[(size_t)i * BSZ + tid];
    const int li = __ldg(labels + i);
    const unsigned nb = __ballot_sync(0xffffffffu, __ldg(labels + tid) != li);
    if (lane == 0) { nmask[warp] = nb; wsum[warp] = 0.f; }
    __syncthreads();

    // Register copy of the 16 neg-mask words (broadcast LDS, cheap)
    unsigned nm[16];
    #pragma unroll
    for (int c = 0; c < 16; c++) nm[c] = nmask[c];

    // fallback index: first negative (argmax over all-False == 0)
    int j0 = 0;
    {
        int found = 0;
        #pragma unroll
        for (int c = 0; c < 16; c++)
            if (!found && nm[c]) { j0 = c * 32 + (__ffs(nm[c]) - 1); found = 1; }
    }
    const float dfb = drow[j0];

    float psum = 0.f;

    // 16 warps stride over candidate positives p in (i, 512)
    for (int p = i + 1 + warp; p < BSZ; p += 16) {
        if ((nm[p >> 5] >> (p & 31)) & 1u) continue;  // not same label (warp-uniform)
        const float dap = drow[p];
        const float hi  = dap + MARGIN;
        int minj = BSZ;
        #pragma unroll
        for (int q = 0; q < 16; q++) {               // j = lane + 32q, increasing
            const int j = q * 32 + lane;
            if (((nm[q] >> lane) & 1u) && drow[j] > dap && drow[j] < hi) {
                minj = j;
                break;
            }
        }
        minj = __reduce_min_sync(0xffffffffu, minj);
        float dan;
        if (minj < BSZ) {
            // rank = #negatives strictly before minj (reference quirk index)
            int r = 0;
            const int mc = minj >> 5, mb = minj & 31;
            #pragma unroll
            for (int c = 0; c < 16; c++)
                if (c < mc) r += __popc(nm[c]);
            r += __popc(nm[mc] & ((1u << mb) - 1u));
            dan = drow[r];
        } else {
            dan = dfb;
        }
        if (lane == 0) {
            const float v = fmaf(dap, dap, MARGIN) - dan * dan;
            psum += v > 0.f ? v : 0.f;
        }
    }
    if (lane == 0) wsum[warp] = psum;
    __syncthreads();

    if (tid == 0) {
        float s = 0.f;
        #pragma unroll
        for (int w = 0; w < 16; w++) s += wsum[w];   // fixed order
        // count of positives with p > i, directly from masks
        int cnt = 0;
        #pragma unroll
        for (int c = 0; c < 16; c++) {
            unsigned gt;
            const int r = i - c * 32;
            if (r < 0)        gt = 0xffffffffu;
            else if (r >= 31) gt = 0u;
            else              gt = 0xffffffffu << (r + 1);
            cnt += __popc((~nmask[c]) & gt);
        }
        g_psum[i] = s;
        g_pcnt[i] = cnt;
        __threadfence();
        const int prev = atomicAdd(&g_ctr, 1);
        sLast = (prev == (int)gridDim.x - 1) ? 1 : 0;
    }
    __syncthreads();

    // last block: deterministic fixed-order final reduction
    if (sLast) {
        __threadfence();
        __shared__ float rs[BSZ];
        __shared__ int   rc[BSZ];
        rs[tid] = g_psum[tid];
        rc[tid] = g_pcnt[tid];
        __syncthreads();
        #pragma unroll
        for (int s = 256; s > 0; s >>= 1) {
            if (tid < s) { rs[tid] += rs[tid + s]; rc[tid] += rc[tid + s]; }
            __syncthreads();
        }
        if (tid == 0) {
            out[0] = rs[0] / (float)rc[0];
            g_ctr  = 0;                   // reset for next graph replay
        }
    }
}

// ---------------------------------------------------------------------------
extern "C" void kernel_launch(void* const* d_in, const int* in_sizes, int n_in,
                              void* d_out, int out_size) {
    const float* emb    = (const float*)d_in[0];
    const int*   labels = (const int*)d_in[1];
    float*       out    = (float*)d_out;

    dim3 gA(16, 16), bA(16, 16);
    dist_kernel<<<gA, bA>>>(emb);
    mine_kernel<<<BSZ, BSZ>>>(labels, out);
}

// round 5
// speedup vs baseline: 1.2770x; 1.2770x over previous
#include <cuda_runtime.h>
#include <cuda_bf16.h>
#include <cstdint>

#define BSZ 512
#define DIM 128
#define MARGIN 0.2f

// Scratch (no allocations anywhere)
__device__ float g_dist[BSZ * BSZ];
__device__ float g_psum[BSZ];
__device__ int   g_pcnt[BSZ];
__device__ int   g_ctr;          // zero-init; last block resets -> replay-safe

// ---- packed f32x2 helpers (Blackwell) -------------------------------------
__device__ __forceinline__ unsigned long long add2(unsigned long long a,
                                                   unsigned long long b) {
    unsigned long long r;
    asm("add.rn.f32x2 %0, %1, %2;" : "=l"(r) : "l"(a), "l"(b));
    return r;
}
__device__ __forceinline__ unsigned long long fma2(unsigned long long a,
                                                   unsigned long long b,
                                                   unsigned long long c) {
    unsigned long long r;
    asm("fma.rn.f32x2 %0, %1, %2, %3;" : "=l"(r) : "l"(a), "l"(b), "l"(c));
    return r;
}
__device__ __forceinline__ float sum2(unsigned long long v) {
    float lo, hi;
    asm("mov.b64 {%0, %1}, %2;" : "=f"(lo), "=f"(hi) : "l"(v));
    return lo + hi;
}

// ---------------------------------------------------------------------------
// Kernel A: pairwise Euclidean dist, diff-based (matches reference's
// sum((a-b)^2)), packed f32x2: sub == add of negated B. 32x32 tile, 2x2 micro.
// ---------------------------------------------------------------------------
__global__ __launch_bounds__(256, 4)
void dist_kernel(const float* __restrict__ emb) {
    __shared__ float sA[32][130];   // 128 + 2 pad (odd ull stride)
    __shared__ float sB[32][130];   // NEGATED B rows

    const int tx = threadIdx.x, ty = threadIdx.y;
    const int tid = ty * 16 + tx;
    const int i0 = blockIdx.y * 32;
    const int j0 = blockIdx.x * 32;

    #pragma unroll
    for (int t = tid; t < 1024; t += 256) {
        const int row = t >> 5;
        const int c4  = t & 31;
        const float4 va = *(const float4*)(emb + (size_t)(i0 + row) * DIM + c4 * 4);
        float2* da = (float2*)&sA[row][c4 * 4];
        da[0] = make_float2(va.x, va.y);
        da[1] = make_float2(va.z, va.w);
        const float4 vb = *(const float4*)(emb + (size_t)(j0 + row) * DIM + c4 * 4);
        float2* db = (float2*)&sB[row][c4 * 4];
        db[0] = make_float2(-vb.x, -vb.y);
        db[1] = make_float2(-vb.z, -vb.w);
    }
    __syncthreads();

    const unsigned long long* A0 = (const unsigned long long*)sA[ty * 2 + 0];
    const unsigned long long* A1 = (const unsigned long long*)sA[ty * 2 + 1];
    const unsigned long long* B0 = (const unsigned long long*)sB[tx * 2 + 0];
    const unsigned long long* B1 = (const unsigned long long*)sB[tx * 2 + 1];

    unsigned long long acc00 = 0ull, acc01 = 0ull, acc10 = 0ull, acc11 = 0ull;

    #pragma unroll 16
    for (int k2 = 0; k2 < 64; k2++) {
        const unsigned long long a0 = A0[k2];
        const unsigned long long a1 = A1[k2];
        const unsigned long long b0 = B0[k2];
        const unsigned long long b1 = B1[k2];
        unsigned long long t;
        t = add2(a0, b0); acc00 = fma2(t, t, acc00);
        t = add2(a0, b1); acc01 = fma2(t, t, acc01);
        t = add2(a1, b0); acc10 = fma2(t, t, acc10);
        t = add2(a1, b1); acc11 = fma2(t, t, acc11);
    }

    const int i = i0 + ty * 2;
    const int j = j0 + tx * 2;
    const float s00 = sum2(acc00), s01 = sum2(acc01);
    const float s10 = sum2(acc10), s11 = sum2(acc11);
    g_dist[(size_t)(i + 0) * BSZ + (j + 0)] = s00 > 0.f ? sqrtf(s00) : 0.f;
    g_dist[(size_t)(i + 0) * BSZ + (j + 1)] = s01 > 0.f ? sqrtf(s01) : 0.f;
    g_dist[(size_t)(i + 1) * BSZ + (j + 0)] = s10 > 0.f ? sqrtf(s10) : 0.f;
    g_dist[(size_t)(i + 1) * BSZ + (j + 1)] = s11 > 0.f ? sqrtf(s11) : 0.f;
}

// ---------------------------------------------------------------------------
// Kernel B: block-per-row mining (512 blocks x 256 thr) + fused finalize.
// Per valid pair (i<p, same label):
//   j_min = first j: neg[j] && d_ap < d[i,j] < d_ap+margin
//   found  -> d_an = d[i, rank(j_min)]   (reference quirk: neg-rank index)
//   !found -> d_an = d[i, j0]            (j0 = first negative, else 0)
//   loss  += relu(d_ap^2 - d_an^2 + margin)
// Inner scan: warp-uniform early exit via one ballot per 32-j chunk.
// ---------------------------------------------------------------------------
__global__ __launch_bounds__(256, 6)
void mine_kernel(const int* __restrict__ labels, float* __restrict__ out) {
    __shared__ float    drow[BSZ];
    __shared__ unsigned nmask[16];      // neg ballot words for this row
    __shared__ float    wsum[8];
    __shared__ int      sLast;

    const int i    = blockIdx.x;
    const int tid  = threadIdx.x;
    const int warp = tid >> 5;
    const int lane = tid & 31;

    // coalesced row load: 256 threads x float2
    ((float2*)drow)[tid] = ((const float2*)(g_dist + (size_t)i * BSZ))[tid];

    const int li = __ldg(labels + i);
    {
        const int l0 = __ldg(labels + warp * 64 + lane);
        const int l1 = __ldg(labels + warp * 64 + 32 + lane);
        const unsigned b0 = __ballot_sync(0xffffffffu, l0 != li);
        const unsigned b1 = __ballot_sync(0xffffffffu, l1 != li);
        if (lane == 0) {
            nmask[warp * 2 + 0] = b0;
            nmask[warp * 2 + 1] = b1;
            wsum[warp] = 0.f;
        }
    }
    __syncthreads();

    // fallback index: first negative (argmax over all-False == 0)
    int j0 = 0;
    #pragma unroll
    for (int c = 15; c >= 0; c--) {
        const unsigned w = nmask[c];
        if (w) j0 = c * 32 + (__ffs(w) - 1);
    }
    const float dfb = drow[j0];

    float psum = 0.f;

    // 8 warps stride over candidate positives p in (i, 512)
    for (int p = i + 1 + warp; p < BSZ; p += 8) {
        if ((nmask[p >> 5] >> (p & 31)) & 1u) continue;  // warp-uniform
        const float dap = drow[p];
        const float hi  = dap + MARGIN;
        int minj = -1;
        #pragma unroll 1
        for (int q = 0; q < 16; q++) {                   // warp-uniform early exit
            const int j = q * 32 + lane;
            const float dj = drow[j];
            const bool hit = ((nmask[q] >> lane) & 1u) && dj > dap && dj < hi;
            const unsigned bm = __ballot_sync(0xffffffffu, hit);
            if (bm) { minj = q * 32 + (__ffs(bm) - 1); break; }
        }
        float dan;
        if (minj >= 0) {
            // rank = #negatives strictly before minj (reference quirk index)
            const int mc = minj >> 5, mb = minj & 31;
            int r = 0;
            #pragma unroll 1
            for (int c = 0; c < mc; c++) r += __popc(nmask[c]);
            r += __popc(nmask[mc] & ((1u << mb) - 1u));
            dan = drow[r];
        } else {
            dan = dfb;
        }
        if (lane == 0) {
            const float v = fmaf(dap, dap, MARGIN) - dan * dan;
            psum += v > 0.f ? v : 0.f;
        }
    }
    if (lane == 0) wsum[warp] = psum;
    __syncthreads();

    if (tid == 0) {
        float s = 0.f;
        #pragma unroll
        for (int w = 0; w < 8; w++) s += wsum[w];        // fixed order
        // count of positives with p > i, from masks
        int cnt = 0;
        #pragma unroll
        for (int c = 0; c < 16; c++) {
            unsigned gt;
            const int r = i - c * 32;
            if (r < 0)        gt = 0xffffffffu;
            else if (r >= 31) gt = 0u;
            else              gt = 0xffffffffu << (r + 1);
            cnt += __popc((~nmask[c]) & gt);
        }
        g_psum[i] = s;
        g_pcnt[i] = cnt;
        __threadfence();
        const int prev = atomicAdd(&g_ctr, 1);
        sLast = (prev == (int)gridDim.x - 1) ? 1 : 0;
    }
    __syncthreads();

    // last block: deterministic fixed-order final reduction
    if (sLast) {
        __threadfence();
        __shared__ float rs[256];
        __shared__ int   rc[256];
        rs[tid] = g_psum[tid] + g_psum[tid + 256];
        rc[tid] = g_pcnt[tid] + g_pcnt[tid + 256];
        __syncthreads();
        #pragma unroll
        for (int s = 128; s > 0; s >>= 1) {
            if (tid < s) { rs[tid] += rs[tid + s]; rc[tid] += rc[tid + s]; }
            __syncthreads();
        }
        if (tid == 0) {
            out[0] = rs[0] / (float)rc[0];
            g_ctr  = 0;                   // reset for next graph replay
        }
    }
}

// ---------------------------------------------------------------------------
extern "C" void kernel_launch(void* const* d_in, const int* in_sizes, int n_in,
                              void* d_out, int out_size) {
    const float* emb    = (const float*)d_in[0];
    const int*   labels = (const int*)d_in[1];
    float*       out    = (float*)d_out;

    dim3 gA(16, 16), bA(16, 16);
    dist_kernel<<<gA, bA>>>(emb);
    mine_kernel<<<BSZ, 256>>>(labels, out);
}

// round 7
// speedup vs baseline: 1.4025x; 1.0983x over previous
#include <cuda_runtime.h>
#include <cuda_bf16.h>
#include <cstdint>

#define BSZ 512
#define DIM 128
#define MARGIN 0.2f
#define RPB 8   // rows (warps) per mining block

// Scratch (no allocations anywhere)
__device__ float g_dist[BSZ * BSZ];
__device__ float g_psum[BSZ];
__device__ int   g_pcnt[BSZ];
__device__ int   g_ctr;          // zero-init; last block resets -> replay-safe

// ---- packed f32x2 helpers (Blackwell) -------------------------------------
__device__ __forceinline__ unsigned long long add2(unsigned long long a,
                                                   unsigned long long b) {
    unsigned long long r;
    asm("add.rn.f32x2 %0, %1, %2;" : "=l"(r) : "l"(a), "l"(b));
    return r;
}
__device__ __forceinline__ unsigned long long fma2(unsigned long long a,
                                                   unsigned long long b,
                                                   unsigned long long c) {
    unsigned long long r;
    asm("fma.rn.f32x2 %0, %1, %2, %3;" : "=l"(r) : "l"(a), "l"(b), "l"(c));
    return r;
}
__device__ __forceinline__ float sum2(unsigned long long v) {
    float lo, hi;
    asm("mov.b64 {%0, %1}, %2;" : "=f"(lo), "=f"(hi) : "l"(v));
    return lo + hi;
}

// ---------------------------------------------------------------------------
// Kernel A: pairwise Euclidean dist, diff-based (matches reference's
// sum((a-b)^2)), packed f32x2: sub == add of negated B. 32x32 tile, 2x2 micro.
// ---------------------------------------------------------------------------
__global__ __launch_bounds__(256, 4)
void dist_kernel(const float* __restrict__ emb) {
    __shared__ float sA[32][130];   // 128 + 2 pad (row stride 520B, 8B-aligned)
    __shared__ float sB[32][130];   // NEGATED B rows

    const int tx = threadIdx.x, ty = threadIdx.y;
    const int tid = ty * 16 + tx;
    const int i0 = blockIdx.y * 32;
    const int j0 = blockIdx.x * 32;

    #pragma unroll
    for (int t = tid; t < 1024; t += 256) {
        const int row = t >> 5;
        const int c4  = t & 31;
        const float4 va = *(const float4*)(emb + (size_t)(i0 + row) * DIM + c4 * 4);
        float2* da = (float2*)&sA[row][c4 * 4];
        da[0] = make_float2(va.x, va.y);
        da[1] = make_float2(va.z, va.w);
        const float4 vb = *(const float4*)(emb + (size_t)(j0 + row) * DIM + c4 * 4);
        float2* db = (float2*)&sB[row][c4 * 4];
        db[0] = make_float2(-vb.x, -vb.y);
        db[1] = make_float2(-vb.z, -vb.w);
    }
    __syncthreads();

    const unsigned long long* A0 = (const unsigned long long*)sA[ty * 2 + 0];
    const unsigned long long* A1 = (const unsigned long long*)sA[ty * 2 + 1];
    const unsigned long long* B0 = (const unsigned long long*)sB[tx * 2 + 0];
    const unsigned long long* B1 = (const unsigned long long*)sB[tx * 2 + 1];

    unsigned long long acc00 = 0ull, acc01 = 0ull, acc10 = 0ull, acc11 = 0ull;

    #pragma unroll 16
    for (int k2 = 0; k2 < 64; k2++) {
        const unsigned long long a0 = A0[k2];
        const unsigned long long a1 = A1[k2];
        const unsigned long long b0 = B0[k2];
        const unsigned long long b1 = B1[k2];
        unsigned long long t;
        t = add2(a0, b0); acc00 = fma2(t, t, acc00);
        t = add2(a0, b1); acc01 = fma2(t, t, acc01);
        t = add2(a1, b0); acc10 = fma2(t, t, acc10);
        t = add2(a1, b1); acc11 = fma2(t, t, acc11);
    }

    const int i = i0 + ty * 2;
    const int j = j0 + tx * 2;
    const float s00 = sum2(acc00), s01 = sum2(acc01);
    const float s10 = sum2(acc10), s11 = sum2(acc11);
    g_dist[(size_t)(i + 0) * BSZ + (j + 0)] = s00 > 0.f ? sqrtf(s00) : 0.f;
    g_dist[(size_t)(i + 0) * BSZ + (j + 1)] = s01 > 0.f ? sqrtf(s01) : 0.f;
    g_dist[(size_t)(i + 1) * BSZ + (j + 0)] = s10 > 0.f ? sqrtf(s10) : 0.f;
    g_dist[(size_t)(i + 1) * BSZ + (j + 1)] = s11 > 0.f ? sqrtf(s11) : 0.f;
}

// ---------------------------------------------------------------------------
// Kernel B: warp-per-row mining, 8 rows/block, 64 blocks + fused finalize.
// Per valid pair (i<p, same label):
//   j_min = first j: neg[j] && d_ap < d[i,j] < d_ap+margin
//   found  -> d_an = d[i, rank(j_min)]   (reference quirk: neg-rank index)
//   !found -> d_an = d[i, j0]            (j0 = first negative, else 0)
//   loss  += relu(d_ap^2 - d_an^2 + margin)
// All warp-scope; positives extracted by bit iteration (no candidate loop).
// ---------------------------------------------------------------------------
__global__ __launch_bounds__(256, 2)
void mine_kernel(const int* __restrict__ labels, float* __restrict__ out) {
    __shared__ float    drow[RPB][BSZ];
    __shared__ unsigned nm[RPB][16];     // neg ballot words
    __shared__ unsigned pwm[RPB][16];    // positive&(p>i) words
    __shared__ int      spf[RPB][16];    // exclusive prefix of neg counts
    __shared__ int      sLast;

    const int tid  = threadIdx.x;
    const int w    = tid >> 5;
    const int lane = tid & 31;
    const int i    = blockIdx.x * RPB + w;

    // row load: 4 float4 per lane (coalesced within warp)
    {
        const float4* rp = (const float4*)(g_dist + (size_t)i * BSZ);
        float4* dst = (float4*)drow[w];
        #pragma unroll
        for (int q = 0; q < 4; q++) dst[q * 32 + lane] = rp[q * 32 + lane];
    }

    const int li = __ldg(labels + i);

    // Build 16 neg ballot words; lane q keeps word q in myneg
    unsigned myneg = 0;
    #pragma unroll
    for (int q = 0; q < 16; q++) {
        const int lab = __ldg(labels + q * 32 + lane);
        const unsigned b = __ballot_sync(0xffffffffu, lab != li);
        if (lane == q) myneg = b;
    }
    if (lane < 16) nm[w][lane] = myneg;

    // positive (p>i) words; cnt of valid pairs
    unsigned myposgt = 0;
    if (lane < 16) {
        const int r = i - lane * 32;
        const unsigned gt = (r < 0) ? 0xffffffffu
                          : (r >= 31 ? 0u : (0xffffffffu << (r + 1)));
        myposgt = (~myneg) & gt;
        pwm[w][lane] = myposgt;
    }
    const int cnt = __reduce_add_sync(0xffffffffu, (lane < 16) ? __popc(myposgt) : 0);

    // exclusive prefix of per-word negative counts (warp shuffle scan)
    {
        const int nc = (lane < 16) ? __popc(myneg) : 0;
        int incl = nc;
        #pragma unroll
        for (int d = 1; d < 16; d <<= 1) {
            const int t = __shfl_up_sync(0xffffffffu, incl, d);
            if (lane >= d) incl += t;
        }
        if (lane < 16) spf[w][lane] = incl - nc;
    }

    // fallback j0 = first negative index (argmax over all-False == 0)
    int j0 = 0;
    {
        const unsigned negany = __ballot_sync(0xffffffffu, lane < 16 && myneg != 0);
        if (negany) {
            const int c0 = __ffs(negany) - 1;
            const unsigned w0 = __shfl_sync(0xffffffffu, myneg, c0);
            j0 = c0 * 32 + (__ffs(w0) - 1);
        }
    }
    unsigned pmask16 = __ballot_sync(0xffffffffu, lane < 16 && myposgt != 0);
    __syncwarp();                       // smem stores visible warp-wide
    const float dfb = drow[w][j0];

    float psum = 0.f;
    while (pmask16) {                    // words containing positives
        const int c = __ffs(pmask16) - 1;
        pmask16 &= pmask16 - 1;
        unsigned pm = pwm[w][c];         // uniform broadcast
        while (pm) {
            const int b = __ffs(pm) - 1;
            pm &= pm - 1;
            const int p = c * 32 + b;
            const float dap = drow[w][p];
            const float hi  = dap + MARGIN;
            int minj = -1;
            #pragma unroll 1
            for (int q = 0; q < 16; q++) {           // warp-uniform early exit
                const float dj = drow[w][q * 32 + lane];
                const bool hit = ((nm[w][q] >> lane) & 1u) && dj > dap && dj < hi;
                const unsigned bm = __ballot_sync(0xffffffffu, hit);
                if (bm) { minj = q * 32 + (__ffs(bm) - 1); break; }
            }
            float dan;
            if (minj >= 0) {
                const int mc = minj >> 5, mb = minj & 31;
                const int rank = spf[w][mc] + __popc(nm[w][mc] & ((1u << mb) - 1u));
                dan = drow[w][rank];     // reference quirk: index by neg-rank
            } else {
                dan = dfb;
            }
            const float v = fmaf(dap, dap, MARGIN) - dan * dan;
            psum += v > 0.f ? v : 0.f;   // uniform across lanes
        }
    }

    if (lane == 0) {
        g_psum[i] = psum;
        g_pcnt[i] = cnt;
        __threadfence();                 // writer-side fence (safe pattern)
    }
    __syncthreads();

    if (tid == 0) {
        const int prev = atomicAdd(&g_ctr, 1);
        sLast = (prev == (int)gridDim.x - 1) ? 1 : 0;
    }
    __syncthreads();

    // last block: deterministic fixed-order final reduction
    if (sLast) {
        __threadfence();
        __shared__ float rs[256];
        __shared__ int   rc[256];
        rs[tid] = g_psum[tid] + g_psum[tid + 256];
        rc[tid] = g_pcnt[tid] + g_pcnt[tid + 256];
        __syncthreads();
        #pragma unroll
        for (int s = 128; s > 0; s >>= 1) {
            if (tid < s) { rs[tid] += rs[tid + s]; rc[tid] += rc[tid + s]; }
            __syncthreads();
        }
        if (tid == 0) {
            out[0] = rs[0] / (float)rc[0];
            g_ctr  = 0;                   // reset for next graph replay
        }
    }
}

// ---------------------------------------------------------------------------
extern "C" void kernel_launch(void* const* d_in, const int* in_sizes, int n_in,
                              void* d_out, int out_size) {
    const float* emb    = (const float*)d_in[0];
    const int*   labels = (const int*)d_in[1];
    float*       out    = (float*)d_out;

    dim3 gA(16, 16), bA(16, 16);
    dist_kernel<<<gA, bA>>>(emb);
    mine_kernel<<<BSZ / RPB, 256>>>(labels, out);
}